// round 12
// baseline (speedup 1.0000x reference)
#include <cuda_runtime.h>
#include <cuda_fp16.h>
#include <stdint.h>

#define B_ 16
#define S_ 2048
#define E_ 1024
#define H_ 64
#define LOG2E 1.4426950408889634f

// fp16 hi/lo pre-split operands. uint2 = {hi_pair(f16x2), lo_pair(f16x2)},
// pairs packed along the MMA k-dimension.
__device__ uint2 g_Q2[B_ * S_ * (H_ / 2)];   // [b][s][dpair]   (Q pre-scaled)
__device__ uint2 g_K2[B_ * S_ * (H_ / 2)];   // [b][s][dpair]
__device__ uint2 g_V2t[B_ * H_ * (S_ / 2)];  // [b][d][spair]   (V transposed)
__device__ uint2 g_W2t[3 * H_ * (E_ / 2)];   // [mat][h][epair] (W transposed)

// ---------------------------------------------------------------------------
// helpers
// ---------------------------------------------------------------------------
__device__ __forceinline__ uint32_t pack_f16(float e0, float e1) {
    __half2 h = __floats2half2_rn(e0, e1);   // low = e0, high = e1
    return *reinterpret_cast<uint32_t*>(&h);
}
__device__ __forceinline__ uint2 split_pair(float e0, float e1) {
    __half2 h = __floats2half2_rn(e0, e1);
    float f0 = __low2float(h), f1 = __high2float(h);
    __half2 l = __floats2half2_rn(e0 - f0, e1 - f1);
    uint2 r;
    r.x = *reinterpret_cast<uint32_t*>(&h);
    r.y = *reinterpret_cast<uint32_t*>(&l);
    return r;
}
__device__ __forceinline__ float ex2(float x) {
    float r;
    asm("ex2.approx.f32 %0, %1;" : "=f"(r) : "f"(x));
    return r;
}
__device__ __forceinline__ void mma16(float* d, uint32_t a0, uint32_t a1,
                                      uint32_t a2, uint32_t a3,
                                      uint32_t b0, uint32_t b1) {
    asm volatile(
        "mma.sync.aligned.m16n8k16.row.col.f32.f16.f16.f32 "
        "{%0,%1,%2,%3}, {%4,%5,%6,%7}, {%8,%9}, {%0,%1,%2,%3};\n"
        : "+f"(d[0]), "+f"(d[1]), "+f"(d[2]), "+f"(d[3])
        : "r"(a0), "r"(a1), "r"(a2), "r"(a3), "r"(b0), "r"(b1));
}
// 3-product emulation: hi*hi + hi*lo + lo*hi
__device__ __forceinline__ void mma3(float* d, uint2 a0, uint2 a1, uint2 a2,
                                     uint2 a3, uint2 b0, uint2 b1) {
    mma16(d, a0.x, a1.x, a2.x, a3.x, b0.x, b1.x);
    mma16(d, a0.x, a1.x, a2.x, a3.x, b0.y, b1.y);
    mma16(d, a0.y, a1.y, a2.y, a3.y, b0.x, b1.x);
}
// 2-product: A_hi * (B_hi + B_lo)
__device__ __forceinline__ void mma2(float* d, uint32_t a0, uint32_t a1,
                                     uint32_t a2, uint32_t a3,
                                     uint2 b0, uint2 b1) {
    mma16(d, a0, a1, a2, a3, b0.x, b1.x);
    mma16(d, a0, a1, a2, a3, b0.y, b1.y);
}
__device__ __forceinline__ void cp16(uint32_t s, const void* g) {
    asm volatile("cp.async.cg.shared.global [%0], [%1], 16;" :: "r"(s), "l"(g));
}
#define CP_COMMIT() asm volatile("cp.async.commit_group;")
#define CP_WAIT1()  asm volatile("cp.async.wait_group 1;")
#define CP_WAIT0()  asm volatile("cp.async.wait_group 0;")

// ---------------------------------------------------------------------------
// W pre-split+transpose prologue
// ---------------------------------------------------------------------------
__global__ void wsplit_kernel(const float* __restrict__ Wq,
                              const float* __restrict__ Wk,
                              const float* __restrict__ Wv)
{
    int idx = blockIdx.x * 256 + threadIdx.x;
    int mat = idx >> 15;
    int h = (idx >> 9) & 63;
    int p = idx & 511;
    const float* W = (mat == 0) ? Wq : (mat == 1 ? Wk : Wv);
    float e0 = W[(2 * p) * H_ + h];
    float e1 = W[(2 * p + 1) * H_ + h];
    g_W2t[idx] = split_pair(e0, e1);
}

// ---------------------------------------------------------------------------
// FUSED QKV projection. grid=256 row-tiles, 384 threads = 3 mat-groups x 4
// warps. One x tile read serves all three mats (L2 traffic /3); each warp
// owns 32 rows (2 m-frags) of one mat. 2-stage cp.async pipeline.
// smem: 2*(128*40*4) + 2*3*(64*20*8) = 102400 B.
// ---------------------------------------------------------------------------
__global__ __launch_bounds__(384) void qkv_kernel(const float* __restrict__ x)
{
    constexpr int SXF = 40;              // fp32 stride
    constexpr int SWP = 20;              // uint2 stride
    constexpr int XSTAGE = 128 * SXF;    // floats per x stage
    constexpr int WSTAGE = 64 * SWP;     // uint2 per W stage per mat
    extern __shared__ float qsm[];
    float* xs_base = qsm;                           // 2 x XSTAGE
    uint2* wt_base = (uint2*)(qsm + 2 * XSTAGE);    // 2 x (3 x WSTAGE)
    uint32_t smb = (uint32_t)__cvta_generic_to_shared(qsm);
    const uint32_t ws_smb = smb + 2 * XSTAGE * 4;

    const int tid = threadIdx.x;
    const int w = tid >> 5;
    const int lane = tid & 31;
    const int gid = lane >> 2;
    const int tig = lane & 3;
    const int mg = w >> 2;      // mat group 0..2
    const int wm = w & 3;       // warp within group: rows wm*32..+32
    const int rbase = blockIdx.x * 128;

    float acc[2][8][4];
#pragma unroll
    for (int mf = 0; mf < 2; mf++)
#pragma unroll
        for (int nt = 0; nt < 8; nt++)
#pragma unroll
            for (int i = 0; i < 4; i++) acc[mf][nt][i] = 0.f;

    auto issue = [&](int it, int buf) {
        // x tile: 128 rows x 32 f32 = 1024 x 16B
        const float* xsrc = x + (size_t)rbase * E_ + it * 32;
        uint32_t xb = smb + buf * (XSTAGE * 4);
        for (int fi = tid; fi < 1024; fi += 384) {
            int r = fi >> 3;
            int c4 = fi & 7;
            cp16(xb + (r * SXF + 4 * c4) * 4, xsrc + (size_t)r * E_ + 4 * c4);
        }
        // W tiles: 3 mats x 64 h x 16 pairs = 1536 x 16B
        uint32_t wb = ws_smb + buf * (3 * WSTAGE * 8);
#pragma unroll
        for (int i = 0; i < 4; i++) {
            int fi = tid + i * 384;
            int m = fi >> 9;
            int h = (fi >> 3) & 63;
            int c4 = fi & 7;
            cp16(wb + ((m * WSTAGE) + h * SWP + 2 * c4) * 8,
                 g_W2t + (size_t)m * 32768 + (size_t)h * 512 + it * 16 + 2 * c4);
        }
    };

    issue(0, 0);
    CP_COMMIT();
    issue(1, 1);
    CP_COMMIT();

    for (int it = 0; it < 32; it++) {
        CP_WAIT1();          // stage it landed
        __syncthreads();

        const float* xs = xs_base + (it & 1) * XSTAGE;
        const uint2* wt = wt_base + (it & 1) * (3 * WSTAGE) + mg * WSTAGE;
        const float* xA = xs + (wm * 32 + gid) * SXF;        // mf0 rows
        const float* xB = xA + 16 * SXF;                     // mf1 rows

#pragma unroll
        for (int ks = 0; ks < 2; ks++) {
            const int pb = ks * 8;
            uint2 a[2][4];
#pragma unroll
            for (int mf = 0; mf < 2; mf++) {
                const float* r0 = (mf == 0) ? xA : xB;
                const float* r1 = r0 + 8 * SXF;
                float2 x00 = *(const float2*)(r0 + 2 * (pb + tig));
                float2 x10 = *(const float2*)(r1 + 2 * (pb + tig));
                float2 x01 = *(const float2*)(r0 + 2 * (pb + tig + 4));
                float2 x11 = *(const float2*)(r1 + 2 * (pb + tig + 4));
                a[mf][0] = split_pair(x00.x, x00.y);
                a[mf][1] = split_pair(x10.x, x10.y);
                a[mf][2] = split_pair(x01.x, x01.y);
                a[mf][3] = split_pair(x11.x, x11.y);
            }
#pragma unroll
            for (int nt = 0; nt < 8; nt++) {
                uint2 b0 = wt[(nt * 8 + gid) * SWP + pb + tig];
                uint2 b1 = wt[(nt * 8 + gid) * SWP + pb + tig + 4];
                mma3(acc[0][nt], a[0][0], a[0][1], a[0][2], a[0][3], b0, b1);
                mma3(acc[1][nt], a[1][0], a[1][1], a[1][2], a[1][3], b0, b1);
            }
        }

        __syncthreads();     // all warps done with stage it (buf it&1)
        if (it + 2 < 32) issue(it + 2, it & 1);
        CP_COMMIT();         // uniform group count
    }

#pragma unroll
    for (int mf = 0; mf < 2; mf++) {
        const int r0 = rbase + wm * 32 + mf * 16 + gid;
        if (mg < 2) {
            uint2* outb = (mg == 0) ? g_Q2 : g_K2;
            const float sc = (mg == 0) ? 0.125f * LOG2E : 1.0f;
#pragma unroll
            for (int nt = 0; nt < 8; nt++) {
                int cp = nt * 4 + tig;
                outb[(size_t)r0 * 32 + cp] =
                    split_pair(acc[mf][nt][0] * sc, acc[mf][nt][1] * sc);
                outb[(size_t)(r0 + 8) * 32 + cp] =
                    split_pair(acc[mf][nt][2] * sc, acc[mf][nt][3] * sc);
            }
        } else {
            // V: transpose via shfl pairing of adjacent rows
            const int bb = r0 >> 11;
            const int sloc = r0 & 2047;
            const size_t vb = (size_t)bb * H_ * (S_ / 2);
#pragma unroll
            for (int nt = 0; nt < 8; nt++) {
                float q00 = __shfl_down_sync(0xffffffffu, acc[mf][nt][0], 4);
                float q01 = __shfl_down_sync(0xffffffffu, acc[mf][nt][1], 4);
                float q10 = __shfl_down_sync(0xffffffffu, acc[mf][nt][2], 4);
                float q11 = __shfl_down_sync(0xffffffffu, acc[mf][nt][3], 4);
                if ((gid & 1) == 0) {
                    int c0 = nt * 8 + 2 * tig;
                    int sp = sloc >> 1;
                    g_V2t[vb + (size_t)c0 * 1024 + sp] =
                        split_pair(acc[mf][nt][0], q00);
                    g_V2t[vb + (size_t)(c0 + 1) * 1024 + sp] =
                        split_pair(acc[mf][nt][1], q01);
                    g_V2t[vb + (size_t)c0 * 1024 + sp + 4] =
                        split_pair(acc[mf][nt][2], q10);
                    g_V2t[vb + (size_t)(c0 + 1) * 1024 + sp + 4] =
                        split_pair(acc[mf][nt][3], q11);
                }
            }
        }
    }
}

// ---------------------------------------------------------------------------
// Flash attention, 128-row q-tiles. 256 threads (8 warps x 16 rows).
// Q in smem; P in registers (S-accumulator layout == PV A-operand layout);
// K/V double-buffered. smem 110592 B -> 2 CTAs/SM (one wave, 256 blocks).
// ---------------------------------------------------------------------------
__global__ __launch_bounds__(256, 2) void attn_kernel(float* __restrict__ out)
{
    constexpr int ST = 36;
    constexpr int QTILE = 128 * ST;          // uint2
    constexpr int KVTILE = 64 * ST;          // uint2
    constexpr uint32_t ONES = 0x3C003C00u;   // (1.0h, 1.0h)
    extern __shared__ uint2 sm2[];
    uint2* Q2s = sm2;                        // 128 x 36
    // K buf b at QTILE + 2b*KVTILE, V buf b at +KVTILE more
    uint32_t smb = (uint32_t)__cvta_generic_to_shared(sm2);

    const int tid = threadIdx.x;
    const int w = tid >> 5;
    const int lane = tid & 31;
    const int gid = lane >> 2;
    const int tig = lane & 3;

    const int qt = 15 - ((int)blockIdx.x >> 4);   // longest-first
    const int b = (int)blockIdx.x & 15;
    const int qbase = qt * 128;
    const int nkt = 2 * qt + 2;

    const uint2* __restrict__ Qg = g_Q2 + (size_t)b * S_ * 32;
    const uint2* __restrict__ Kg = g_K2 + (size_t)b * S_ * 32;
    const uint2* __restrict__ Vg = g_V2t + (size_t)b * H_ * 1024;

    auto issue_kv = [&](int kt, int buf) {
        const int kbase = kt * 64;
        const int kb2 = kt * 32;
        uint32_t kb = smb + (QTILE + 2 * buf * KVTILE) * 8;
        uint32_t vb = kb + KVTILE * 8;
#pragma unroll
        for (int i = 0; i < 4; i++) {
            int fi = tid + i * 256;
            int r = fi >> 4;
            int c4 = fi & 15;
            cp16(kb + (r * ST + 2 * c4) * 8,
                 Kg + (size_t)(kbase + r) * 32 + 2 * c4);
            cp16(vb + (r * ST + 2 * c4) * 8,
                 Vg + (size_t)r * 1024 + kb2 + 2 * c4);
        }
    };

    // Prologue: Q (128 rows x 16 c4 = 2048 cp16) + (K0,V0) group 0; (K1,V1) group 1.
#pragma unroll
    for (int i = 0; i < 8; i++) {
        int fi = tid + i * 256;
        int r = fi >> 4;
        int c4 = fi & 15;
        cp16(smb + (r * ST + 2 * c4) * 8,
             Qg + (size_t)(qbase + r) * 32 + 2 * c4);
    }
    issue_kv(0, 0);
    CP_COMMIT();
    issue_kv(1, 1);     // nkt >= 2 always
    CP_COMMIT();

    const int row0 = qbase + w * 16 + gid;
    const int row1 = row0 + 8;

    float o[8][4];
#pragma unroll
    for (int nt = 0; nt < 8; nt++)
#pragma unroll
        for (int i = 0; i < 4; i++) o[nt][i] = 0.f;
    float m0 = -1e30f, m1 = -1e30f, l0 = 0.f, l1 = 0.f;

    const uint2* qr0 = Q2s + (w * 16 + gid) * ST;
    const uint2* qr1 = qr0 + 8 * ST;

    for (int kt = 0; kt < nkt; kt++) {
        CP_WAIT1();          // tiles for kt landed
        __syncthreads();

        const uint2* K2s = sm2 + QTILE + 2 * (kt & 1) * KVTILE;
        const uint2* V2s = K2s + KVTILE;

        // ---- S = Q K^T (16 x 64 per warp), 3-product fp16 ----
        float s[8][4];
#pragma unroll
        for (int nt = 0; nt < 8; nt++)
#pragma unroll
            for (int i = 0; i < 4; i++) s[nt][i] = 0.f;
#pragma unroll
        for (int ks = 0; ks < 4; ks++) {
            const int pb = ks * 8;
            uint2 a0 = qr0[pb + tig];
            uint2 a1 = qr1[pb + tig];
            uint2 a2 = qr0[pb + tig + 4];
            uint2 a3 = qr1[pb + tig + 4];
#pragma unroll
            for (int nt = 0; nt < 8; nt++) {
                uint2 b0 = K2s[(nt * 8 + gid) * ST + pb + tig];
                uint2 b1 = K2s[(nt * 8 + gid) * ST + pb + tig + 4];
                mma3(s[nt], a0, a1, a2, a3, b0, b1);
            }
        }

        // ---- causal mask (diagonal band: last two key tiles) + row max ----
        float mloc0 = -1e30f, mloc1 = -1e30f;
        if (kt >= nkt - 2) {
            const int kbase = kt * 64;
#pragma unroll
            for (int nt = 0; nt < 8; nt++) {
                int c0 = kbase + nt * 8 + 2 * tig;
                int c1 = c0 + 1;
                s[nt][0] = (c0 <= row0) ? s[nt][0] : -1e30f;
                s[nt][1] = (c1 <= row0) ? s[nt][1] : -1e30f;
                s[nt][2] = (c0 <= row1) ? s[nt][2] : -1e30f;
                s[nt][3] = (c1 <= row1) ? s[nt][3] : -1e30f;
                mloc0 = fmaxf(mloc0, fmaxf(s[nt][0], s[nt][1]));
                mloc1 = fmaxf(mloc1, fmaxf(s[nt][2], s[nt][3]));
            }
        } else {
#pragma unroll
            for (int nt = 0; nt < 8; nt++) {
                mloc0 = fmaxf(mloc0, fmaxf(s[nt][0], s[nt][1]));
                mloc1 = fmaxf(mloc1, fmaxf(s[nt][2], s[nt][3]));
            }
        }
        mloc0 = fmaxf(mloc0, __shfl_xor_sync(0xffffffffu, mloc0, 1));
        mloc0 = fmaxf(mloc0, __shfl_xor_sync(0xffffffffu, mloc0, 2));
        mloc1 = fmaxf(mloc1, __shfl_xor_sync(0xffffffffu, mloc1, 1));
        mloc1 = fmaxf(mloc1, __shfl_xor_sync(0xffffffffu, mloc1, 2));

        float mn0 = fmaxf(m0, mloc0);
        float mn1 = fmaxf(m1, mloc1);
        float corr0 = ex2(m0 - mn0);
        float corr1 = ex2(m1 - mn1);
        m0 = mn0; m1 = mn1;
        l0 *= corr0; l1 *= corr1;

        // ---- P = 2^(s-mn), f32 SFU; stays in registers ----
#pragma unroll
        for (int nt = 0; nt < 8; nt++) {
            s[nt][0] = ex2(s[nt][0] - mn0);
            s[nt][1] = ex2(s[nt][1] - mn0);
            s[nt][2] = ex2(s[nt][2] - mn1);
            s[nt][3] = ex2(s[nt][3] - mn1);
        }
#pragma unroll
        for (int nt = 0; nt < 8; nt++) {
            o[nt][0] *= corr0; o[nt][1] *= corr0;
            o[nt][2] *= corr1; o[nt][3] *= corr1;
        }

        // ---- PV + row-sum: S-accumulator layout == PV A-operand layout ----
        float ps[4] = {0.f, 0.f, 0.f, 0.f};
#pragma unroll
        for (int ks = 0; ks < 4; ks++) {
            const int pb = ks * 8;
            uint32_t a0 = pack_f16(s[2 * ks][0], s[2 * ks][1]);
            uint32_t a1 = pack_f16(s[2 * ks][2], s[2 * ks][3]);
            uint32_t a2 = pack_f16(s[2 * ks + 1][0], s[2 * ks + 1][1]);
            uint32_t a3 = pack_f16(s[2 * ks + 1][2], s[2 * ks + 1][3]);
            mma16(ps, a0, a1, a2, a3, ONES, ONES);
#pragma unroll
            for (int nt = 0; nt < 8; nt++) {
                uint2 b0 = V2s[(nt * 8 + gid) * ST + pb + tig];
                uint2 b1 = V2s[(nt * 8 + gid) * ST + pb + tig + 4];
                mma2(o[nt], a0, a1, a2, a3, b0, b1);
            }
        }
        l0 += ps[0];
        l1 += ps[2];

        __syncthreads();     // all warps done with buf (kt&1)
        if (kt + 2 < nkt) issue_kv(kt + 2, kt & 1);
        CP_COMMIT();         // uniform group count
    }

    const float inv0 = 1.f / l0;
    const float inv1 = 1.f / l1;
#pragma unroll
    for (int nt = 0; nt < 8; nt++) {
        int c = nt * 8 + 2 * tig;
        *(float2*)&out[(size_t)((size_t)b * S_ + row0) * H_ + c] =
            make_float2(o[nt][0] * inv0, o[nt][1] * inv0);
        *(float2*)&out[(size_t)((size_t)b * S_ + row1) * H_ + c] =
            make_float2(o[nt][2] * inv1, o[nt][3] * inv1);
    }
}

// ---------------------------------------------------------------------------
extern "C" void kernel_launch(void* const* d_in, const int* in_sizes, int n_in,
                              void* d_out, int out_size)
{
    const float* x  = (const float*)d_in[0];
    const float* Wq = (const float*)d_in[1];
    const float* Wk = (const float*)d_in[2];
    const float* Wv = (const float*)d_in[3];
    float* out = (float*)d_out;
    (void)in_sizes; (void)n_in; (void)out_size;

    wsplit_kernel<<<384, 256>>>(Wq, Wk, Wv);

    const int qkv_smem = 2 * (128 * 40 * 4) + 2 * 3 * (64 * 20 * 8);  // 102400
    cudaFuncSetAttribute(qkv_kernel,
                         cudaFuncAttributeMaxDynamicSharedMemorySize, qkv_smem);
    qkv_kernel<<<256, 384, qkv_smem>>>(x);

    const int attn_smem = (128 * 36 + 4 * 64 * 36) * 8;  // 110592
    cudaFuncSetAttribute(attn_kernel,
                         cudaFuncAttributeMaxDynamicSharedMemorySize, attn_smem);
    attn_kernel<<<256, 256, attn_smem>>>(out);
}

// round 13
// speedup vs baseline: 1.0778x; 1.0778x over previous
#include <cuda_runtime.h>
#include <cuda_fp16.h>
#include <stdint.h>

#define B_ 16
#define S_ 2048
#define E_ 1024
#define H_ 64
#define LOG2E 1.4426950408889634f

// fp16 hi/lo pre-split operands. uint2 = {hi_pair(f16x2), lo_pair(f16x2)},
// pairs packed along the MMA k-dimension.
__device__ uint2 g_Q2[B_ * S_ * (H_ / 2)];   // [b][s][dpair]   (Q pre-scaled)
__device__ uint2 g_K2[B_ * S_ * (H_ / 2)];   // [b][s][dpair]
__device__ uint2 g_V2t[B_ * H_ * (S_ / 2)];  // [b][d][spair]   (V transposed)
__device__ uint2 g_W2t[3 * H_ * (E_ / 2)];   // [mat][h][epair] (W transposed)

// ---------------------------------------------------------------------------
// helpers
// ---------------------------------------------------------------------------
__device__ __forceinline__ uint32_t pack_f16(float e0, float e1) {
    __half2 h = __floats2half2_rn(e0, e1);   // low = e0, high = e1
    return *reinterpret_cast<uint32_t*>(&h);
}
__device__ __forceinline__ uint2 split_pair(float e0, float e1) {
    __half2 h = __floats2half2_rn(e0, e1);
    float f0 = __low2float(h), f1 = __high2float(h);
    __half2 l = __floats2half2_rn(e0 - f0, e1 - f1);
    uint2 r;
    r.x = *reinterpret_cast<uint32_t*>(&h);
    r.y = *reinterpret_cast<uint32_t*>(&l);
    return r;
}
__device__ __forceinline__ float ex2(float x) {
    float r;
    asm("ex2.approx.f32 %0, %1;" : "=f"(r) : "f"(x));
    return r;
}
__device__ __forceinline__ void mma16(float* d, uint32_t a0, uint32_t a1,
                                      uint32_t a2, uint32_t a3,
                                      uint32_t b0, uint32_t b1) {
    asm volatile(
        "mma.sync.aligned.m16n8k16.row.col.f32.f16.f16.f32 "
        "{%0,%1,%2,%3}, {%4,%5,%6,%7}, {%8,%9}, {%0,%1,%2,%3};\n"
        : "+f"(d[0]), "+f"(d[1]), "+f"(d[2]), "+f"(d[3])
        : "r"(a0), "r"(a1), "r"(a2), "r"(a3), "r"(b0), "r"(b1));
}
// 3-product emulation: hi*hi + hi*lo + lo*hi
__device__ __forceinline__ void mma3(float* d, uint2 a0, uint2 a1, uint2 a2,
                                     uint2 a3, uint2 b0, uint2 b1) {
    mma16(d, a0.x, a1.x, a2.x, a3.x, b0.x, b1.x);
    mma16(d, a0.x, a1.x, a2.x, a3.x, b0.y, b1.y);
    mma16(d, a0.y, a1.y, a2.y, a3.y, b0.x, b1.x);
}
// 2-product: A_hi * (B_hi + B_lo)
__device__ __forceinline__ void mma2(float* d, uint32_t a0, uint32_t a1,
                                     uint32_t a2, uint32_t a3,
                                     uint2 b0, uint2 b1) {
    mma16(d, a0, a1, a2, a3, b0.x, b1.x);
    mma16(d, a0, a1, a2, a3, b0.y, b1.y);
}
__device__ __forceinline__ void cp16(uint32_t s, const void* g) {
    asm volatile("cp.async.cg.shared.global [%0], [%1], 16;" :: "r"(s), "l"(g));
}
#define CP_COMMIT() asm volatile("cp.async.commit_group;")
#define CP_WAIT1()  asm volatile("cp.async.wait_group 1;")
#define CP_WAIT0()  asm volatile("cp.async.wait_group 0;")

// ---------------------------------------------------------------------------
// W pre-split+transpose prologue
// ---------------------------------------------------------------------------
__global__ void wsplit_kernel(const float* __restrict__ Wq,
                              const float* __restrict__ Wk,
                              const float* __restrict__ Wv)
{
    int idx = blockIdx.x * 256 + threadIdx.x;
    int mat = idx >> 15;
    int h = (idx >> 9) & 63;
    int p = idx & 511;
    const float* W = (mat == 0) ? Wq : (mat == 1 ? Wk : Wv);
    float e0 = W[(2 * p) * H_ + h];
    float e1 = W[(2 * p + 1) * H_ + h];
    g_W2t[idx] = split_pair(e0, e1);
}

// ---------------------------------------------------------------------------
// QKV projection (R8 exact). grid=(3 mats, 256 rowtiles) — mat fast dim so
// the 3 blocks sharing one x row-tile are co-resident => x hits L2.
// 256 threads (8 warps), 3-stage cp.async pipeline, one barrier per iter.
// smem 92160 B.
// ---------------------------------------------------------------------------
__global__ __launch_bounds__(256) void qkv_kernel(const float* __restrict__ x)
{
    constexpr int SXF = 40;
    constexpr int SWP = 20;
    constexpr int XSTAGE = 128 * SXF;
    constexpr int WSTAGE = 64 * SWP;
    extern __shared__ float qsm[];
    float* xs_base = qsm;
    uint2* wt_base = (uint2*)(qsm + 3 * XSTAGE);
    uint32_t smb = (uint32_t)__cvta_generic_to_shared(qsm);
    const uint32_t ws_smb = smb + 3 * XSTAGE * 4;

    const int mat = blockIdx.x;
    const int tid = threadIdx.x;
    const int w = tid >> 5;
    const int lane = tid & 31;
    const int gid = lane >> 2;
    const int tig = lane & 3;
    const int rbase = blockIdx.y * 128;

    const uint2* __restrict__ wsrc = g_W2t + mat * (H_ * (E_ / 2));

    float acc[8][4];
#pragma unroll
    for (int nt = 0; nt < 8; nt++)
#pragma unroll
        for (int i = 0; i < 4; i++) acc[nt][i] = 0.f;

    auto issue = [&](int it, int buf) {
        const float* xsrc = x + (size_t)rbase * E_ + it * 32;
        uint32_t xb = smb + buf * (XSTAGE * 4);
#pragma unroll
        for (int i = 0; i < 4; i++) {
            int fi = tid + i * 256;
            int r = fi >> 3;
            int c4 = fi & 7;
            cp16(xb + (r * SXF + 4 * c4) * 4, xsrc + (size_t)r * E_ + 4 * c4);
        }
        uint32_t wb = ws_smb + buf * (WSTAGE * 8);
        const uint2* wp = wsrc + it * 16;
#pragma unroll
        for (int i = 0; i < 2; i++) {
            int fi = tid + i * 256;
            int h = fi >> 3;
            int c4 = fi & 7;
            cp16(wb + (h * SWP + 2 * c4) * 8, wp + (size_t)h * 512 + 2 * c4);
        }
    };

    issue(0, 0);
    CP_COMMIT();
    issue(1, 1);
    CP_COMMIT();

    for (int it = 0; it < 32; it++) {
        CP_WAIT1();
        __syncthreads();
        if (it + 2 < 32) issue(it + 2, (it + 2) % 3);
        CP_COMMIT();

        const float* xs = xs_base + (it % 3) * XSTAGE;
        const uint2* wt = wt_base + (it % 3) * WSTAGE;
        const float* xr0 = xs + (w * 16 + gid) * SXF;
        const float* xr1 = xr0 + 8 * SXF;

#pragma unroll
        for (int ks = 0; ks < 2; ks++) {
            const int pb = ks * 8;
            float2 x00 = *(const float2*)(xr0 + 2 * (pb + tig));
            float2 x10 = *(const float2*)(xr1 + 2 * (pb + tig));
            float2 x01 = *(const float2*)(xr0 + 2 * (pb + tig + 4));
            float2 x11 = *(const float2*)(xr1 + 2 * (pb + tig + 4));
            uint2 a0 = split_pair(x00.x, x00.y);
            uint2 a1 = split_pair(x10.x, x10.y);
            uint2 a2 = split_pair(x01.x, x01.y);
            uint2 a3 = split_pair(x11.x, x11.y);
#pragma unroll
            for (int nt = 0; nt < 8; nt++) {
                uint2 b0 = wt[(nt * 8 + gid) * SWP + pb + tig];
                uint2 b1 = wt[(nt * 8 + gid) * SWP + pb + tig + 4];
                mma3(acc[nt], a0, a1, a2, a3, b0, b1);
            }
        }
    }

    const int r0 = rbase + w * 16 + gid;
    if (mat < 2) {
        uint2* outb = (mat == 0) ? g_Q2 : g_K2;
        const float sc = (mat == 0) ? 0.125f * LOG2E : 1.0f;
#pragma unroll
        for (int nt = 0; nt < 8; nt++) {
            int cp = nt * 4 + tig;
            outb[(size_t)r0 * 32 + cp] =
                split_pair(acc[nt][0] * sc, acc[nt][1] * sc);
            outb[(size_t)(r0 + 8) * 32 + cp] =
                split_pair(acc[nt][2] * sc, acc[nt][3] * sc);
        }
    } else {
        const int bb = r0 >> 11;
        const int sloc = r0 & 2047;
        const size_t vb = (size_t)bb * H_ * (S_ / 2);
#pragma unroll
        for (int nt = 0; nt < 8; nt++) {
            float q00 = __shfl_down_sync(0xffffffffu, acc[nt][0], 4);
            float q01 = __shfl_down_sync(0xffffffffu, acc[nt][1], 4);
            float q10 = __shfl_down_sync(0xffffffffu, acc[nt][2], 4);
            float q11 = __shfl_down_sync(0xffffffffu, acc[nt][3], 4);
            if ((gid & 1) == 0) {
                int c0 = nt * 8 + 2 * tig;
                int sp = sloc >> 1;
                g_V2t[vb + (size_t)c0 * 1024 + sp] = split_pair(acc[nt][0], q00);
                g_V2t[vb + (size_t)(c0 + 1) * 1024 + sp] = split_pair(acc[nt][1], q01);
                g_V2t[vb + (size_t)c0 * 1024 + sp + 4] = split_pair(acc[nt][2], q10);
                g_V2t[vb + (size_t)(c0 + 1) * 1024 + sp + 4] = split_pair(acc[nt][3], q11);
            }
        }
    }
}

// ---------------------------------------------------------------------------
// Flash attention (R8 structure; P kept in registers via the accumulator-
// layout identity; l via ones-MMA). grid=512 (1D longest-first), 128 threads
// (4 warps). smem: Q + 2xK + 2xV = 92160 B, launch_bounds(128,2).
// ---------------------------------------------------------------------------
__global__ __launch_bounds__(128, 2) void attn_kernel(float* __restrict__ out)
{
    constexpr int ST = 36;
    constexpr int TILE = 64 * ST;            // uint2 per tile
    constexpr uint32_t ONES = 0x3C003C00u;   // (1.0h, 1.0h)
    extern __shared__ uint2 sm2[];
    uint2* Q2s = sm2;                        // tile 0
    // K buf b = tile 1+2b, V buf b = tile 2+2b
    uint32_t smb = (uint32_t)__cvta_generic_to_shared(sm2);

    const int tid = threadIdx.x;
    const int w = tid >> 5;
    const int lane = tid & 31;
    const int gid = lane >> 2;
    const int tig = lane & 3;

    const int qt = 31 - ((int)blockIdx.x >> 4);   // longest-first
    const int b = (int)blockIdx.x & 15;
    const int qbase = qt * 64;

    const uint2* __restrict__ Qg = g_Q2 + (size_t)b * S_ * 32;
    const uint2* __restrict__ Kg = g_K2 + (size_t)b * S_ * 32;
    const uint2* __restrict__ Vg = g_V2t + (size_t)b * H_ * 1024;

    auto issue_kv = [&](int kt, int buf) {
        const int kbase = kt * 64;
        const int kb2 = kt * 32;
        uint32_t kb = smb + (1 + 2 * buf) * TILE * 8;
        uint32_t vb = smb + (2 + 2 * buf) * TILE * 8;
#pragma unroll
        for (int i = 0; i < 8; i++) {
            int fi = tid + i * 128;
            int r = fi >> 4;
            int c4 = fi & 15;
            cp16(kb + (r * ST + 2 * c4) * 8,
                 Kg + (size_t)(kbase + r) * 32 + 2 * c4);
            cp16(vb + (r * ST + 2 * c4) * 8,
                 Vg + (size_t)r * 1024 + kb2 + 2 * c4);
        }
    };

    // Prologue: Q + (K0,V0) group 0; (K1,V1) group 1.
#pragma unroll
    for (int i = 0; i < 8; i++) {
        int fi = tid + i * 128;
        int r = fi >> 4;
        int c4 = fi & 15;
        cp16(smb + (r * ST + 2 * c4) * 8,
             Qg + (size_t)(qbase + r) * 32 + 2 * c4);
    }
    issue_kv(0, 0);
    CP_COMMIT();
    if (qt >= 1) issue_kv(1, 1);
    CP_COMMIT();

    const int row0 = qbase + w * 16 + gid;
    const int row1 = row0 + 8;

    float o[8][4];
#pragma unroll
    for (int nt = 0; nt < 8; nt++)
#pragma unroll
        for (int i = 0; i < 4; i++) o[nt][i] = 0.f;
    float m0 = -1e30f, m1 = -1e30f, l0 = 0.f, l1 = 0.f;

    const uint2* qr0 = Q2s + (w * 16 + gid) * ST;
    const uint2* qr1 = qr0 + 8 * ST;

    for (int kt = 0; kt <= qt; kt++) {
        CP_WAIT1();          // tiles for kt landed
        __syncthreads();

        const uint2* K2s = sm2 + (1 + 2 * (kt & 1)) * TILE;
        const uint2* V2s = sm2 + (2 + 2 * (kt & 1)) * TILE;

        // ---- S = Q K^T (16 x 64 per warp), 3-product fp16 ----
        float s[8][4];
#pragma unroll
        for (int nt = 0; nt < 8; nt++)
#pragma unroll
            for (int i = 0; i < 4; i++) s[nt][i] = 0.f;
#pragma unroll
        for (int ks = 0; ks < 4; ks++) {
            const int pb = ks * 8;
            uint2 a0 = qr0[pb + tig];
            uint2 a1 = qr1[pb + tig];
            uint2 a2 = qr0[pb + tig + 4];
            uint2 a3 = qr1[pb + tig + 4];
#pragma unroll
            for (int nt = 0; nt < 8; nt++) {
                uint2 b0 = K2s[(nt * 8 + gid) * ST + pb + tig];
                uint2 b1 = K2s[(nt * 8 + gid) * ST + pb + tig + 4];
                mma3(s[nt], a0, a1, a2, a3, b0, b1);
            }
        }

        // ---- causal mask (diagonal tile only) + row max ----
        float mloc0 = -1e30f, mloc1 = -1e30f;
        if (kt == qt) {
            const int kbase = kt * 64;
#pragma unroll
            for (int nt = 0; nt < 8; nt++) {
                int c0 = kbase + nt * 8 + 2 * tig;
                int c1 = c0 + 1;
                s[nt][0] = (c0 <= row0) ? s[nt][0] : -1e30f;
                s[nt][1] = (c1 <= row0) ? s[nt][1] : -1e30f;
                s[nt][2] = (c0 <= row1) ? s[nt][2] : -1e30f;
                s[nt][3] = (c1 <= row1) ? s[nt][3] : -1e30f;
                mloc0 = fmaxf(mloc0, fmaxf(s[nt][0], s[nt][1]));
                mloc1 = fmaxf(mloc1, fmaxf(s[nt][2], s[nt][3]));
            }
        } else {
#pragma unroll
            for (int nt = 0; nt < 8; nt++) {
                mloc0 = fmaxf(mloc0, fmaxf(s[nt][0], s[nt][1]));
                mloc1 = fmaxf(mloc1, fmaxf(s[nt][2], s[nt][3]));
            }
        }
        mloc0 = fmaxf(mloc0, __shfl_xor_sync(0xffffffffu, mloc0, 1));
        mloc0 = fmaxf(mloc0, __shfl_xor_sync(0xffffffffu, mloc0, 2));
        mloc1 = fmaxf(mloc1, __shfl_xor_sync(0xffffffffu, mloc1, 1));
        mloc1 = fmaxf(mloc1, __shfl_xor_sync(0xffffffffu, mloc1, 2));

        float mn0 = fmaxf(m0, mloc0);
        float mn1 = fmaxf(m1, mloc1);
        float corr0 = ex2(m0 - mn0);
        float corr1 = ex2(m1 - mn1);
        m0 = mn0; m1 = mn1;
        l0 *= corr0; l1 *= corr1;

        // ---- P = 2^(s-mn), f32 SFU; stays in registers ----
#pragma unroll
        for (int nt = 0; nt < 8; nt++) {
            s[nt][0] = ex2(s[nt][0] - mn0);
            s[nt][1] = ex2(s[nt][1] - mn0);
            s[nt][2] = ex2(s[nt][2] - mn1);
            s[nt][3] = ex2(s[nt][3] - mn1);
        }
#pragma unroll
        for (int nt = 0; nt < 8; nt++) {
            o[nt][0] *= corr0; o[nt][1] *= corr0;
            o[nt][2] *= corr1; o[nt][3] *= corr1;
        }

        // ---- PV + row-sum: S-accumulator layout == PV A-operand layout ----
        float ps[4] = {0.f, 0.f, 0.f, 0.f};
#pragma unroll
        for (int ks = 0; ks < 4; ks++) {
            const int pb = ks * 8;
            uint32_t a0 = pack_f16(s[2 * ks][0], s[2 * ks][1]);
            uint32_t a1 = pack_f16(s[2 * ks][2], s[2 * ks][3]);
            uint32_t a2 = pack_f16(s[2 * ks + 1][0], s[2 * ks + 1][1]);
            uint32_t a3 = pack_f16(s[2 * ks + 1][2], s[2 * ks + 1][3]);
            mma16(ps, a0, a1, a2, a3, ONES, ONES);
#pragma unroll
            for (int nt = 0; nt < 8; nt++) {
                uint2 b0 = V2s[(nt * 8 + gid) * ST + pb + tig];
                uint2 b1 = V2s[(nt * 8 + gid) * ST + pb + tig + 4];
                mma2(o[nt], a0, a1, a2, a3, b0, b1);
            }
        }
        l0 += ps[0];
        l1 += ps[2];

        __syncthreads();     // all warps done with buf (kt&1)
        if (kt + 2 <= qt) issue_kv(kt + 2, kt & 1);
        CP_COMMIT();         // uniform group count
    }

    const float inv0 = 1.f / l0;
    const float inv1 = 1.f / l1;
#pragma unroll
    for (int nt = 0; nt < 8; nt++) {
        int c = nt * 8 + 2 * tig;
        *(float2*)&out[(size_t)((size_t)b * S_ + row0) * H_ + c] =
            make_float2(o[nt][0] * inv0, o[nt][1] * inv0);
        *(float2*)&out[(size_t)((size_t)b * S_ + row1) * H_ + c] =
            make_float2(o[nt][2] * inv1, o[nt][3] * inv1);
    }
}

// ---------------------------------------------------------------------------
extern "C" void kernel_launch(void* const* d_in, const int* in_sizes, int n_in,
                              void* d_out, int out_size)
{
    const float* x  = (const float*)d_in[0];
    const float* Wq = (const float*)d_in[1];
    const float* Wk = (const float*)d_in[2];
    const float* Wv = (const float*)d_in[3];
    float* out = (float*)d_out;
    (void)in_sizes; (void)n_in; (void)out_size;

    wsplit_kernel<<<384, 256>>>(Wq, Wk, Wv);

    const int qkv_smem = 3 * (128 * 40 * 4 + 64 * 20 * 8);  // 92160
    cudaFuncSetAttribute(qkv_kernel,
                         cudaFuncAttributeMaxDynamicSharedMemorySize, qkv_smem);
    qkv_kernel<<<dim3(3, 256), 256, qkv_smem>>>(x);

    const int attn_smem = 5 * 64 * 36 * 8;  // 92160: Q + 2K + 2V
    cudaFuncSetAttribute(attn_kernel,
                         cudaFuncAttributeMaxDynamicSharedMemorySize, attn_smem);
    attn_kernel<<<512, 128, attn_smem>>>(out);
}

// round 16
// speedup vs baseline: 1.0972x; 1.0179x over previous
#include <cuda_runtime.h>
#include <cuda_fp16.h>
#include <stdint.h>

#define B_ 16
#define S_ 2048
#define E_ 1024
#define H_ 64
#define LOG2E 1.4426950408889634f

// fp16 hi/lo pre-split operands. uint2 = {hi_pair(f16x2), lo_pair(f16x2)},
// pairs packed along the MMA k-dimension.
__device__ uint2 g_Q2[B_ * S_ * (H_ / 2)];   // [b][s][dpair]   (Q pre-scaled)
__device__ uint2 g_K2[B_ * S_ * (H_ / 2)];   // [b][s][dpair]
__device__ uint2 g_V2t[B_ * H_ * (S_ / 2)];  // [b][d][spair]   (V transposed)
__device__ uint2 g_W2t[3 * H_ * (E_ / 2)];   // [mat][h][epair] (W transposed)

// ---------------------------------------------------------------------------
// helpers
// ---------------------------------------------------------------------------
__device__ __forceinline__ uint32_t pack_f16(float e0, float e1) {
    __half2 h = __floats2half2_rn(e0, e1);   // low = e0, high = e1
    return *reinterpret_cast<uint32_t*>(&h);
}
__device__ __forceinline__ uint2 split_pair(float e0, float e1) {
    __half2 h = __floats2half2_rn(e0, e1);
    float f0 = __low2float(h), f1 = __high2float(h);
    __half2 l = __floats2half2_rn(e0 - f0, e1 - f1);
    uint2 r;
    r.x = *reinterpret_cast<uint32_t*>(&h);
    r.y = *reinterpret_cast<uint32_t*>(&l);
    return r;
}
__device__ __forceinline__ float ex2(float x) {
    float r;
    asm("ex2.approx.f32 %0, %1;" : "=f"(r) : "f"(x));
    return r;
}
__device__ __forceinline__ void mma16(float* d, uint32_t a0, uint32_t a1,
                                      uint32_t a2, uint32_t a3,
                                      uint32_t b0, uint32_t b1) {
    asm volatile(
        "mma.sync.aligned.m16n8k16.row.col.f32.f16.f16.f32 "
        "{%0,%1,%2,%3}, {%4,%5,%6,%7}, {%8,%9}, {%0,%1,%2,%3};\n"
        : "+f"(d[0]), "+f"(d[1]), "+f"(d[2]), "+f"(d[3])
        : "r"(a0), "r"(a1), "r"(a2), "r"(a3), "r"(b0), "r"(b1));
}
// 3-product emulation: hi*hi + hi*lo + lo*hi
__device__ __forceinline__ void mma3(float* d, uint2 a0, uint2 a1, uint2 a2,
                                     uint2 a3, uint2 b0, uint2 b1) {
    mma16(d, a0.x, a1.x, a2.x, a3.x, b0.x, b1.x);
    mma16(d, a0.x, a1.x, a2.x, a3.x, b0.y, b1.y);
    mma16(d, a0.y, a1.y, a2.y, a3.y, b0.x, b1.x);
}
// 2-product: A_hi * (B_hi + B_lo)
__device__ __forceinline__ void mma2(float* d, uint32_t a0, uint32_t a1,
                                     uint32_t a2, uint32_t a3,
                                     uint2 b0, uint2 b1) {
    mma16(d, a0, a1, a2, a3, b0.x, b1.x);
    mma16(d, a0, a1, a2, a3, b0.y, b1.y);
}
__device__ __forceinline__ void cp16(uint32_t s, const void* g) {
    asm volatile("cp.async.cg.shared.global [%0], [%1], 16;" :: "r"(s), "l"(g));
}
#define CP_COMMIT() asm volatile("cp.async.commit_group;")
#define CP_WAIT1()  asm volatile("cp.async.wait_group 1;")
#define CP_WAIT0()  asm volatile("cp.async.wait_group 0;")

// ---------------------------------------------------------------------------
// W pre-split+transpose prologue
// ---------------------------------------------------------------------------
__global__ void wsplit_kernel(const float* __restrict__ Wq,
                              const float* __restrict__ Wk,
                              const float* __restrict__ Wv)
{
    int idx = blockIdx.x * 256 + threadIdx.x;
    int mat = idx >> 15;
    int h = (idx >> 9) & 63;
    int p = idx & 511;
    const float* W = (mat == 0) ? Wq : (mat == 1 ? Wk : Wv);
    float e0 = W[(2 * p) * H_ + h];
    float e1 = W[(2 * p + 1) * H_ + h];
    g_W2t[idx] = split_pair(e0, e1);
}

// ---------------------------------------------------------------------------
// QKV projection (R13 exact). grid=(3 mats, 256 rowtiles), 256 threads,
// 3-stage cp.async pipeline, one barrier per iter. smem 92160 B.
// ---------------------------------------------------------------------------
__global__ __launch_bounds__(256) void qkv_kernel(const float* __restrict__ x)
{
    constexpr int SXF = 40;
    constexpr int SWP = 20;
    constexpr int XSTAGE = 128 * SXF;
    constexpr int WSTAGE = 64 * SWP;
    extern __shared__ float qsm[];
    float* xs_base = qsm;
    uint2* wt_base = (uint2*)(qsm + 3 * XSTAGE);
    uint32_t smb = (uint32_t)__cvta_generic_to_shared(qsm);
    const uint32_t ws_smb = smb + 3 * XSTAGE * 4;

    const int mat = blockIdx.x;
    const int tid = threadIdx.x;
    const int w = tid >> 5;
    const int lane = tid & 31;
    const int gid = lane >> 2;
    const int tig = lane & 3;
    const int rbase = blockIdx.y * 128;

    const uint2* __restrict__ wsrc = g_W2t + mat * (H_ * (E_ / 2));

    float acc[8][4];
#pragma unroll
    for (int nt = 0; nt < 8; nt++)
#pragma unroll
        for (int i = 0; i < 4; i++) acc[nt][i] = 0.f;

    auto issue = [&](int it, int buf) {
        const float* xsrc = x + (size_t)rbase * E_ + it * 32;
        uint32_t xb = smb + buf * (XSTAGE * 4);
#pragma unroll
        for (int i = 0; i < 4; i++) {
            int fi = tid + i * 256;
            int r = fi >> 3;
            int c4 = fi & 7;
            cp16(xb + (r * SXF + 4 * c4) * 4, xsrc + (size_t)r * E_ + 4 * c4);
        }
        uint32_t wb = ws_smb + buf * (WSTAGE * 8);
        const uint2* wp = wsrc + it * 16;
#pragma unroll
        for (int i = 0; i < 2; i++) {
            int fi = tid + i * 256;
            int h = fi >> 3;
            int c4 = fi & 7;
            cp16(wb + (h * SWP + 2 * c4) * 8, wp + (size_t)h * 512 + 2 * c4);
        }
    };

    issue(0, 0);
    CP_COMMIT();
    issue(1, 1);
    CP_COMMIT();

    for (int it = 0; it < 32; it++) {
        CP_WAIT1();
        __syncthreads();
        if (it + 2 < 32) issue(it + 2, (it + 2) % 3);
        CP_COMMIT();

        const float* xs = xs_base + (it % 3) * XSTAGE;
        const uint2* wt = wt_base + (it % 3) * WSTAGE;
        const float* xr0 = xs + (w * 16 + gid) * SXF;
        const float* xr1 = xr0 + 8 * SXF;

#pragma unroll
        for (int ks = 0; ks < 2; ks++) {
            const int pb = ks * 8;
            float2 x00 = *(const float2*)(xr0 + 2 * (pb + tig));
            float2 x10 = *(const float2*)(xr1 + 2 * (pb + tig));
            float2 x01 = *(const float2*)(xr0 + 2 * (pb + tig + 4));
            float2 x11 = *(const float2*)(xr1 + 2 * (pb + tig + 4));
            uint2 a0 = split_pair(x00.x, x00.y);
            uint2 a1 = split_pair(x10.x, x10.y);
            uint2 a2 = split_pair(x01.x, x01.y);
            uint2 a3 = split_pair(x11.x, x11.y);
#pragma unroll
            for (int nt = 0; nt < 8; nt++) {
                uint2 b0 = wt[(nt * 8 + gid) * SWP + pb + tig];
                uint2 b1 = wt[(nt * 8 + gid) * SWP + pb + tig + 4];
                mma3(acc[nt], a0, a1, a2, a3, b0, b1);
            }
        }
    }

    const int r0 = rbase + w * 16 + gid;
    if (mat < 2) {
        uint2* outb = (mat == 0) ? g_Q2 : g_K2;
        const float sc = (mat == 0) ? 0.125f * LOG2E : 1.0f;
#pragma unroll
        for (int nt = 0; nt < 8; nt++) {
            int cp = nt * 4 + tig;
            outb[(size_t)r0 * 32 + cp] =
                split_pair(acc[nt][0] * sc, acc[nt][1] * sc);
            outb[(size_t)(r0 + 8) * 32 + cp] =
                split_pair(acc[nt][2] * sc, acc[nt][3] * sc);
        }
    } else {
        const int bb = r0 >> 11;
        const int sloc = r0 & 2047;
        const size_t vb = (size_t)bb * H_ * (S_ / 2);
#pragma unroll
        for (int nt = 0; nt < 8; nt++) {
            float q00 = __shfl_down_sync(0xffffffffu, acc[nt][0], 4);
            float q01 = __shfl_down_sync(0xffffffffu, acc[nt][1], 4);
            float q10 = __shfl_down_sync(0xffffffffu, acc[nt][2], 4);
            float q11 = __shfl_down_sync(0xffffffffu, acc[nt][3], 4);
            if ((gid & 1) == 0) {
                int c0 = nt * 8 + 2 * tig;
                int sp = sloc >> 1;
                g_V2t[vb + (size_t)c0 * 1024 + sp] = split_pair(acc[nt][0], q00);
                g_V2t[vb + (size_t)(c0 + 1) * 1024 + sp] = split_pair(acc[nt][1], q01);
                g_V2t[vb + (size_t)c0 * 1024 + sp + 4] = split_pair(acc[nt][2], q10);
                g_V2t[vb + (size_t)(c0 + 1) * 1024 + sp + 4] = split_pair(acc[nt][3], q11);
            }
        }
    }
}

// ---------------------------------------------------------------------------
// Flash attention (R13 + Q-in-registers at safe occupancy).
// grid=512 (1D longest-first), 128 threads (4 warps), launch_bounds(128,2):
// 256 regs/thread available -> qa[4][4] (32 regs) cannot spill.
// smem: 2xK + 2xV only = 73728 B. P stays in registers (layout identity);
// l via ones-MMA.
// ---------------------------------------------------------------------------
__global__ __launch_bounds__(128, 2) void attn_kernel(float* __restrict__ out)
{
    constexpr int ST = 36;
    constexpr int TILE = 64 * ST;            // uint2 per tile
    constexpr uint32_t ONES = 0x3C003C00u;   // (1.0h, 1.0h)
    extern __shared__ uint2 sm2[];
    // K buf b = tile 2b, V buf b = tile 2b+1
    uint32_t smb = (uint32_t)__cvta_generic_to_shared(sm2);

    const int tid = threadIdx.x;
    const int w = tid >> 5;
    const int lane = tid & 31;
    const int gid = lane >> 2;
    const int tig = lane & 3;

    const int qt = 31 - ((int)blockIdx.x >> 4);   // longest-first
    const int b = (int)blockIdx.x & 15;
    const int qbase = qt * 64;

    const uint2* __restrict__ Qg = g_Q2 + (size_t)b * S_ * 32;
    const uint2* __restrict__ Kg = g_K2 + (size_t)b * S_ * 32;
    const uint2* __restrict__ Vg = g_V2t + (size_t)b * H_ * 1024;

    auto issue_kv = [&](int kt, int buf) {
        const int kbase = kt * 64;
        const int kb2 = kt * 32;
        uint32_t kb = smb + (2 * buf) * TILE * 8;
        uint32_t vb = smb + (2 * buf + 1) * TILE * 8;
#pragma unroll
        for (int i = 0; i < 8; i++) {
            int fi = tid + i * 128;
            int r = fi >> 4;
            int c4 = fi & 15;
            cp16(kb + (r * ST + 2 * c4) * 8,
                 Kg + (size_t)(kbase + r) * 32 + 2 * c4);
            cp16(vb + (r * ST + 2 * c4) * 8,
                 Vg + (size_t)r * 1024 + kb2 + 2 * c4);
        }
    };

    issue_kv(0, 0);
    CP_COMMIT();
    if (qt >= 1) issue_kv(1, 1);
    CP_COMMIT();

    const int row0 = qbase + w * 16 + gid;
    const int row1 = row0 + 8;

    // Q fragments: loop-invariant, straight from gmem (L2-hot; overlaps with
    // the in-flight cp.async KV prologue).
    uint2 qa[4][4];
    {
        const uint2* Qr0 = Qg + (size_t)row0 * 32;
        const uint2* Qr1 = Qg + (size_t)row1 * 32;
#pragma unroll
        for (int ks = 0; ks < 4; ks++) {
            qa[ks][0] = Qr0[8 * ks + tig];
            qa[ks][1] = Qr1[8 * ks + tig];
            qa[ks][2] = Qr0[8 * ks + tig + 4];
            qa[ks][3] = Qr1[8 * ks + tig + 4];
        }
    }

    float o[8][4];
#pragma unroll
    for (int nt = 0; nt < 8; nt++)
#pragma unroll
        for (int i = 0; i < 4; i++) o[nt][i] = 0.f;
    float m0 = -1e30f, m1 = -1e30f, l0 = 0.f, l1 = 0.f;

    for (int kt = 0; kt <= qt; kt++) {
        CP_WAIT1();          // tiles for kt landed
        __syncthreads();

        const uint2* K2s = sm2 + (2 * (kt & 1)) * TILE;
        const uint2* V2s = sm2 + (2 * (kt & 1) + 1) * TILE;

        // ---- S = Q K^T (16 x 64 per warp), 3-product fp16, Q from regs ----
        float s[8][4];
#pragma unroll
        for (int nt = 0; nt < 8; nt++)
#pragma unroll
            for (int i = 0; i < 4; i++) s[nt][i] = 0.f;
#pragma unroll
        for (int ks = 0; ks < 4; ks++) {
            const int pb = ks * 8;
#pragma unroll
            for (int nt = 0; nt < 8; nt++) {
                uint2 b0 = K2s[(nt * 8 + gid) * ST + pb + tig];
                uint2 b1 = K2s[(nt * 8 + gid) * ST + pb + tig + 4];
                mma3(s[nt], qa[ks][0], qa[ks][1], qa[ks][2], qa[ks][3],
                     b0, b1);
            }
        }

        // ---- causal mask (diagonal tile only) + row max ----
        float mloc0 = -1e30f, mloc1 = -1e30f;
        if (kt == qt) {
            const int kbase = kt * 64;
#pragma unroll
            for (int nt = 0; nt < 8; nt++) {
                int c0 = kbase + nt * 8 + 2 * tig;
                int c1 = c0 + 1;
                s[nt][0] = (c0 <= row0) ? s[nt][0] : -1e30f;
                s[nt][1] = (c1 <= row0) ? s[nt][1] : -1e30f;
                s[nt][2] = (c0 <= row1) ? s[nt][2] : -1e30f;
                s[nt][3] = (c1 <= row1) ? s[nt][3] : -1e30f;
                mloc0 = fmaxf(mloc0, fmaxf(s[nt][0], s[nt][1]));
                mloc1 = fmaxf(mloc1, fmaxf(s[nt][2], s[nt][3]));
            }
        } else {
#pragma unroll
            for (int nt = 0; nt < 8; nt++) {
                mloc0 = fmaxf(mloc0, fmaxf(s[nt][0], s[nt][1]));
                mloc1 = fmaxf(mloc1, fmaxf(s[nt][2], s[nt][3]));
            }
        }
        mloc0 = fmaxf(mloc0, __shfl_xor_sync(0xffffffffu, mloc0, 1));
        mloc0 = fmaxf(mloc0, __shfl_xor_sync(0xffffffffu, mloc0, 2));
        mloc1 = fmaxf(mloc1, __shfl_xor_sync(0xffffffffu, mloc1, 1));
        mloc1 = fmaxf(mloc1, __shfl_xor_sync(0xffffffffu, mloc1, 2));

        float mn0 = fmaxf(m0, mloc0);
        float mn1 = fmaxf(m1, mloc1);
        float corr0 = ex2(m0 - mn0);
        float corr1 = ex2(m1 - mn1);
        m0 = mn0; m1 = mn1;
        l0 *= corr0; l1 *= corr1;

        // ---- P = 2^(s-mn), f32 SFU; stays in registers ----
#pragma unroll
        for (int nt = 0; nt < 8; nt++) {
            s[nt][0] = ex2(s[nt][0] - mn0);
            s[nt][1] = ex2(s[nt][1] - mn0);
            s[nt][2] = ex2(s[nt][2] - mn1);
            s[nt][3] = ex2(s[nt][3] - mn1);
        }
#pragma unroll
        for (int nt = 0; nt < 8; nt++) {
            o[nt][0] *= corr0; o[nt][1] *= corr0;
            o[nt][2] *= corr1; o[nt][3] *= corr1;
        }

        // ---- PV + row-sum: S-accumulator layout == PV A-operand layout ----
        float ps[4] = {0.f, 0.f, 0.f, 0.f};
#pragma unroll
        for (int ks = 0; ks < 4; ks++) {
            const int pb = ks * 8;
            uint32_t a0 = pack_f16(s[2 * ks][0], s[2 * ks][1]);
            uint32_t a1 = pack_f16(s[2 * ks][2], s[2 * ks][3]);
            uint32_t a2 = pack_f16(s[2 * ks + 1][0], s[2 * ks + 1][1]);
            uint32_t a3 = pack_f16(s[2 * ks + 1][2], s[2 * ks + 1][3]);
            mma16(ps, a0, a1, a2, a3, ONES, ONES);
#pragma unroll
            for (int nt = 0; nt < 8; nt++) {
                uint2 b0 = V2s[(nt * 8 + gid) * ST + pb + tig];
                uint2 b1 = V2s[(nt * 8 + gid) * ST + pb + tig + 4];
                mma2(o[nt], a0, a1, a2, a3, b0, b1);
            }
        }
        l0 += ps[0];
        l1 += ps[2];

        __syncthreads();     // all warps done with buf (kt&1)
        if (kt + 2 <= qt) issue_kv(kt + 2, kt & 1);
        CP_COMMIT();         // uniform group count
    }

    const float inv0 = 1.f / l0;
    const float inv1 = 1.f / l1;
#pragma unroll
    for (int nt = 0; nt < 8; nt++) {
        int c = nt * 8 + 2 * tig;
        *(float2*)&out[(size_t)((size_t)b * S_ + row0) * H_ + c] =
            make_float2(o[nt][0] * inv0, o[nt][1] * inv0);
        *(float2*)&out[(size_t)((size_t)b * S_ + row1) * H_ + c] =
            make_float2(o[nt][2] * inv1, o[nt][3] * inv1);
    }
}

// ---------------------------------------------------------------------------
extern "C" void kernel_launch(void* const* d_in, const int* in_sizes, int n_in,
                              void* d_out, int out_size)
{
    const float* x  = (const float*)d_in[0];
    const float* Wq = (const float*)d_in[1];
    const float* Wk = (const float*)d_in[2];
    const float* Wv = (const float*)d_in[3];
    float* out = (float*)d_out;
    (void)in_sizes; (void)n_in; (void)out_size;

    wsplit_kernel<<<384, 256>>>(Wq, Wk, Wv);

    const int qkv_smem = 3 * (128 * 40 * 4 + 64 * 20 * 8);  // 92160
    cudaFuncSetAttribute(qkv_kernel,
                         cudaFuncAttributeMaxDynamicSharedMemorySize, qkv_smem);
    qkv_kernel<<<dim3(3, 256), 256, qkv_smem>>>(x);

    const int attn_smem = 4 * 64 * 36 * 8;  // 73728: 2K + 2V
    cudaFuncSetAttribute(attn_kernel,
                         cudaFuncAttributeMaxDynamicSharedMemorySize, attn_smem);
    attn_kernel<<<512, 128, attn_smem>>>(out);
}

// round 17
// speedup vs baseline: 1.1902x; 1.0848x over previous
#include <cuda_runtime.h>
#include <cuda_fp16.h>
#include <stdint.h>

#define B_ 16
#define S_ 2048
#define E_ 1024
#define H_ 64
#define LOG2E 1.4426950408889634f

// fp16 hi/lo pre-split operands. uint2 = {hi_pair(f16x2), lo_pair(f16x2)},
// pairs packed along the MMA k-dimension.
__device__ uint2 g_Q2[B_ * S_ * (H_ / 2)];   // [b][s][dpair]   (Q pre-scaled)
__device__ uint2 g_K2[B_ * S_ * (H_ / 2)];   // [b][s][dpair]
__device__ uint2 g_V2t[B_ * H_ * (S_ / 2)];  // [b][d][spair]   (V transposed)
__device__ uint2 g_W2t[3 * H_ * (E_ / 2)];   // [mat][h][epair] (W transposed)

// ---------------------------------------------------------------------------
// helpers
// ---------------------------------------------------------------------------
__device__ __forceinline__ uint32_t pack_f16(float e0, float e1) {
    __half2 h = __floats2half2_rn(e0, e1);   // low = e0, high = e1
    return *reinterpret_cast<uint32_t*>(&h);
}
__device__ __forceinline__ uint2 split_pair(float e0, float e1) {
    __half2 h = __floats2half2_rn(e0, e1);
    float f0 = __low2float(h), f1 = __high2float(h);
    __half2 l = __floats2half2_rn(e0 - f0, e1 - f1);
    uint2 r;
    r.x = *reinterpret_cast<uint32_t*>(&h);
    r.y = *reinterpret_cast<uint32_t*>(&l);
    return r;
}
__device__ __forceinline__ float ex2(float x) {
    float r;
    asm("ex2.approx.f32 %0, %1;" : "=f"(r) : "f"(x));
    return r;
}
__device__ __forceinline__ void mma16(float* d, uint32_t a0, uint32_t a1,
                                      uint32_t a2, uint32_t a3,
                                      uint32_t b0, uint32_t b1) {
    asm volatile(
        "mma.sync.aligned.m16n8k16.row.col.f32.f16.f16.f32 "
        "{%0,%1,%2,%3}, {%4,%5,%6,%7}, {%8,%9}, {%0,%1,%2,%3};\n"
        : "+f"(d[0]), "+f"(d[1]), "+f"(d[2]), "+f"(d[3])
        : "r"(a0), "r"(a1), "r"(a2), "r"(a3), "r"(b0), "r"(b1));
}
// 3-product emulation: hi*hi + hi*lo + lo*hi
__device__ __forceinline__ void mma3(float* d, uint2 a0, uint2 a1, uint2 a2,
                                     uint2 a3, uint2 b0, uint2 b1) {
    mma16(d, a0.x, a1.x, a2.x, a3.x, b0.x, b1.x);
    mma16(d, a0.x, a1.x, a2.x, a3.x, b0.y, b1.y);
    mma16(d, a0.y, a1.y, a2.y, a3.y, b0.x, b1.x);
}
// 2-product: A_hi * (B_hi + B_lo)
__device__ __forceinline__ void mma2(float* d, uint32_t a0, uint32_t a1,
                                     uint32_t a2, uint32_t a3,
                                     uint2 b0, uint2 b1) {
    mma16(d, a0, a1, a2, a3, b0.x, b1.x);
    mma16(d, a0, a1, a2, a3, b0.y, b1.y);
}
__device__ __forceinline__ void cp16(uint32_t s, const void* g) {
    asm volatile("cp.async.cg.shared.global [%0], [%1], 16;" :: "r"(s), "l"(g));
}
#define CP_COMMIT() asm volatile("cp.async.commit_group;")
#define CP_WAIT1()  asm volatile("cp.async.wait_group 1;")
#define CP_WAIT0()  asm volatile("cp.async.wait_group 0;")

// ---------------------------------------------------------------------------
// W pre-split+transpose prologue
// ---------------------------------------------------------------------------
__global__ void wsplit_kernel(const float* __restrict__ Wq,
                              const float* __restrict__ Wk,
                              const float* __restrict__ Wv)
{
    int idx = blockIdx.x * 256 + threadIdx.x;
    int mat = idx >> 15;
    int h = (idx >> 9) & 63;
    int p = idx & 511;
    const float* W = (mat == 0) ? Wq : (mat == 1 ? Wk : Wv);
    float e0 = W[(2 * p) * H_ + h];
    float e1 = W[(2 * p + 1) * H_ + h];
    g_W2t[idx] = split_pair(e0, e1);
}

// ---------------------------------------------------------------------------
// QKV projection. grid=(3 mats, 256 rowtiles), 256 threads, 3-stage pipeline.
// 2-PRODUCT: Q/K/V = x_hi * (W_hi + W_lo)  (x quantized to fp16; W exact).
// Inner loop: 32 HMMA per warp-iter (was 48); x lo-split deleted.
// smem 92160 B.
// ---------------------------------------------------------------------------
__global__ __launch_bounds__(256) void qkv_kernel(const float* __restrict__ x)
{
    constexpr int SXF = 40;
    constexpr int SWP = 20;
    constexpr int XSTAGE = 128 * SXF;
    constexpr int WSTAGE = 64 * SWP;
    extern __shared__ float qsm[];
    float* xs_base = qsm;
    uint2* wt_base = (uint2*)(qsm + 3 * XSTAGE);
    uint32_t smb = (uint32_t)__cvta_generic_to_shared(qsm);
    const uint32_t ws_smb = smb + 3 * XSTAGE * 4;

    const int mat = blockIdx.x;
    const int tid = threadIdx.x;
    const int w = tid >> 5;
    const int lane = tid & 31;
    const int gid = lane >> 2;
    const int tig = lane & 3;
    const int rbase = blockIdx.y * 128;

    const uint2* __restrict__ wsrc = g_W2t + mat * (H_ * (E_ / 2));

    float acc[8][4];
#pragma unroll
    for (int nt = 0; nt < 8; nt++)
#pragma unroll
        for (int i = 0; i < 4; i++) acc[nt][i] = 0.f;

    auto issue = [&](int it, int buf) {
        const float* xsrc = x + (size_t)rbase * E_ + it * 32;
        uint32_t xb = smb + buf * (XSTAGE * 4);
#pragma unroll
        for (int i = 0; i < 4; i++) {
            int fi = tid + i * 256;
            int r = fi >> 3;
            int c4 = fi & 7;
            cp16(xb + (r * SXF + 4 * c4) * 4, xsrc + (size_t)r * E_ + 4 * c4);
        }
        uint32_t wb = ws_smb + buf * (WSTAGE * 8);
        const uint2* wp = wsrc + it * 16;
#pragma unroll
        for (int i = 0; i < 2; i++) {
            int fi = tid + i * 256;
            int h = fi >> 3;
            int c4 = fi & 7;
            cp16(wb + (h * SWP + 2 * c4) * 8, wp + (size_t)h * 512 + 2 * c4);
        }
    };

    issue(0, 0);
    CP_COMMIT();
    issue(1, 1);
    CP_COMMIT();

    for (int it = 0; it < 32; it++) {
        CP_WAIT1();
        __syncthreads();
        if (it + 2 < 32) issue(it + 2, (it + 2) % 3);
        CP_COMMIT();

        const float* xs = xs_base + (it % 3) * XSTAGE;
        const uint2* wt = wt_base + (it % 3) * WSTAGE;
        const float* xr0 = xs + (w * 16 + gid) * SXF;
        const float* xr1 = xr0 + 8 * SXF;

#pragma unroll
        for (int ks = 0; ks < 2; ks++) {
            const int pb = ks * 8;
            float2 x00 = *(const float2*)(xr0 + 2 * (pb + tig));
            float2 x10 = *(const float2*)(xr1 + 2 * (pb + tig));
            float2 x01 = *(const float2*)(xr0 + 2 * (pb + tig + 4));
            float2 x11 = *(const float2*)(xr1 + 2 * (pb + tig + 4));
            uint32_t a0 = pack_f16(x00.x, x00.y);
            uint32_t a1 = pack_f16(x10.x, x10.y);
            uint32_t a2 = pack_f16(x01.x, x01.y);
            uint32_t a3 = pack_f16(x11.x, x11.y);
#pragma unroll
            for (int nt = 0; nt < 8; nt++) {
                uint2 b0 = wt[(nt * 8 + gid) * SWP + pb + tig];
                uint2 b1 = wt[(nt * 8 + gid) * SWP + pb + tig + 4];
                mma2(acc[nt], a0, a1, a2, a3, b0, b1);
            }
        }
    }

    const int r0 = rbase + w * 16 + gid;
    if (mat < 2) {
        uint2* outb = (mat == 0) ? g_Q2 : g_K2;
        const float sc = (mat == 0) ? 0.125f * LOG2E : 1.0f;
#pragma unroll
        for (int nt = 0; nt < 8; nt++) {
            int cp = nt * 4 + tig;
            outb[(size_t)r0 * 32 + cp] =
                split_pair(acc[nt][0] * sc, acc[nt][1] * sc);
            outb[(size_t)(r0 + 8) * 32 + cp] =
                split_pair(acc[nt][2] * sc, acc[nt][3] * sc);
        }
    } else {
        const int bb = r0 >> 11;
        const int sloc = r0 & 2047;
        const size_t vb = (size_t)bb * H_ * (S_ / 2);
#pragma unroll
        for (int nt = 0; nt < 8; nt++) {
            float q00 = __shfl_down_sync(0xffffffffu, acc[nt][0], 4);
            float q01 = __shfl_down_sync(0xffffffffu, acc[nt][1], 4);
            float q10 = __shfl_down_sync(0xffffffffu, acc[nt][2], 4);
            float q11 = __shfl_down_sync(0xffffffffu, acc[nt][3], 4);
            if ((gid & 1) == 0) {
                int c0 = nt * 8 + 2 * tig;
                int sp = sloc >> 1;
                g_V2t[vb + (size_t)c0 * 1024 + sp] = split_pair(acc[nt][0], q00);
                g_V2t[vb + (size_t)(c0 + 1) * 1024 + sp] = split_pair(acc[nt][1], q01);
                g_V2t[vb + (size_t)c0 * 1024 + sp + 4] = split_pair(acc[nt][2], q10);
                g_V2t[vb + (size_t)(c0 + 1) * 1024 + sp + 4] = split_pair(acc[nt][3], q11);
            }
        }
    }
}

// ---------------------------------------------------------------------------
// Flash attention: PAIRED TILES for a balanced single wave.
// grid=256: block (p = bx>>4, b = bx&15) runs qt = 31-p then qt = p
// sequentially -> every block does exactly 33 iterations + 2 prologues;
// 256 blocks <= 296 slots (2 CTAs/SM) -> one wave, zero imbalance.
// Inner loop identical to R16 (Q frags in regs, P in regs, l via ones-MMA).
// smem: 2xK + 2xV = 73728 B.
// ---------------------------------------------------------------------------
__global__ __launch_bounds__(128, 2) void attn_kernel(float* __restrict__ out)
{
    constexpr int ST = 36;
    constexpr int TILE = 64 * ST;            // uint2 per tile
    constexpr uint32_t ONES = 0x3C003C00u;   // (1.0h, 1.0h)
    extern __shared__ uint2 sm2[];
    uint32_t smb = (uint32_t)__cvta_generic_to_shared(sm2);

    const int tid = threadIdx.x;
    const int w = tid >> 5;
    const int lane = tid & 31;
    const int gid = lane >> 2;
    const int tig = lane & 3;

    const int p = (int)blockIdx.x >> 4;      // 0..15
    const int b = (int)blockIdx.x & 15;

    const uint2* __restrict__ Qg = g_Q2 + (size_t)b * S_ * 32;
    const uint2* __restrict__ Kg = g_K2 + (size_t)b * S_ * 32;
    const uint2* __restrict__ Vg = g_V2t + (size_t)b * H_ * 1024;

    auto issue_kv = [&](int kt, int buf) {
        const int kbase = kt * 64;
        const int kb2 = kt * 32;
        uint32_t kb = smb + (2 * buf) * TILE * 8;
        uint32_t vb = smb + (2 * buf + 1) * TILE * 8;
#pragma unroll
        for (int i = 0; i < 8; i++) {
            int fi = tid + i * 128;
            int r = fi >> 4;
            int c4 = fi & 15;
            cp16(kb + (r * ST + 2 * c4) * 8,
                 Kg + (size_t)(kbase + r) * 32 + 2 * c4);
            cp16(vb + (r * ST + 2 * c4) * 8,
                 Vg + (size_t)r * 1024 + kb2 + 2 * c4);
        }
    };

    for (int task = 0; task < 2; task++) {
        const int qt = (task == 0) ? (31 - p) : p;
        const int qbase = qt * 64;
        const int row0 = qbase + w * 16 + gid;
        const int row1 = row0 + 8;

        // KV prologue (buffers safe: previous task's readers passed their
        // final __syncthreads before reaching here).
        issue_kv(0, 0);
        CP_COMMIT();
        if (qt >= 1) issue_kv(1, 1);
        CP_COMMIT();

        // Q fragments: loop-invariant, from gmem (L2-hot), overlap cp.async.
        uint2 qa[4][4];
        {
            const uint2* Qr0 = Qg + (size_t)row0 * 32;
            const uint2* Qr1 = Qg + (size_t)row1 * 32;
#pragma unroll
            for (int ks = 0; ks < 4; ks++) {
                qa[ks][0] = Qr0[8 * ks + tig];
                qa[ks][1] = Qr1[8 * ks + tig];
                qa[ks][2] = Qr0[8 * ks + tig + 4];
                qa[ks][3] = Qr1[8 * ks + tig + 4];
            }
        }

        float o[8][4];
#pragma unroll
        for (int nt = 0; nt < 8; nt++)
#pragma unroll
            for (int i = 0; i < 4; i++) o[nt][i] = 0.f;
        float m0 = -1e30f, m1 = -1e30f, l0 = 0.f, l1 = 0.f;

        for (int kt = 0; kt <= qt; kt++) {
            CP_WAIT1();          // tiles for kt landed
            __syncthreads();

            const uint2* K2s = sm2 + (2 * (kt & 1)) * TILE;
            const uint2* V2s = sm2 + (2 * (kt & 1) + 1) * TILE;

            // ---- S = Q K^T (16 x 64 per warp), 3-product, Q from regs ----
            float s[8][4];
#pragma unroll
            for (int nt = 0; nt < 8; nt++)
#pragma unroll
                for (int i = 0; i < 4; i++) s[nt][i] = 0.f;
#pragma unroll
            for (int ks = 0; ks < 4; ks++) {
                const int pb = ks * 8;
#pragma unroll
                for (int nt = 0; nt < 8; nt++) {
                    uint2 b0 = K2s[(nt * 8 + gid) * ST + pb + tig];
                    uint2 b1 = K2s[(nt * 8 + gid) * ST + pb + tig + 4];
                    mma3(s[nt], qa[ks][0], qa[ks][1], qa[ks][2], qa[ks][3],
                         b0, b1);
                }
            }

            // ---- causal mask (diagonal tile only) + row max ----
            float mloc0 = -1e30f, mloc1 = -1e30f;
            if (kt == qt) {
                const int kbase = kt * 64;
#pragma unroll
                for (int nt = 0; nt < 8; nt++) {
                    int c0 = kbase + nt * 8 + 2 * tig;
                    int c1 = c0 + 1;
                    s[nt][0] = (c0 <= row0) ? s[nt][0] : -1e30f;
                    s[nt][1] = (c1 <= row0) ? s[nt][1] : -1e30f;
                    s[nt][2] = (c0 <= row1) ? s[nt][2] : -1e30f;
                    s[nt][3] = (c1 <= row1) ? s[nt][3] : -1e30f;
                    mloc0 = fmaxf(mloc0, fmaxf(s[nt][0], s[nt][1]));
                    mloc1 = fmaxf(mloc1, fmaxf(s[nt][2], s[nt][3]));
                }
            } else {
#pragma unroll
                for (int nt = 0; nt < 8; nt++) {
                    mloc0 = fmaxf(mloc0, fmaxf(s[nt][0], s[nt][1]));
                    mloc1 = fmaxf(mloc1, fmaxf(s[nt][2], s[nt][3]));
                }
            }
            mloc0 = fmaxf(mloc0, __shfl_xor_sync(0xffffffffu, mloc0, 1));
            mloc0 = fmaxf(mloc0, __shfl_xor_sync(0xffffffffu, mloc0, 2));
            mloc1 = fmaxf(mloc1, __shfl_xor_sync(0xffffffffu, mloc1, 1));
            mloc1 = fmaxf(mloc1, __shfl_xor_sync(0xffffffffu, mloc1, 2));

            float mn0 = fmaxf(m0, mloc0);
            float mn1 = fmaxf(m1, mloc1);
            float corr0 = ex2(m0 - mn0);
            float corr1 = ex2(m1 - mn1);
            m0 = mn0; m1 = mn1;
            l0 *= corr0; l1 *= corr1;

            // ---- P = 2^(s-mn), f32 SFU; stays in registers ----
#pragma unroll
            for (int nt = 0; nt < 8; nt++) {
                s[nt][0] = ex2(s[nt][0] - mn0);
                s[nt][1] = ex2(s[nt][1] - mn0);
                s[nt][2] = ex2(s[nt][2] - mn1);
                s[nt][3] = ex2(s[nt][3] - mn1);
            }
#pragma unroll
            for (int nt = 0; nt < 8; nt++) {
                o[nt][0] *= corr0; o[nt][1] *= corr0;
                o[nt][2] *= corr1; o[nt][3] *= corr1;
            }

            // ---- PV + row-sum (S-accum layout == PV A-operand layout) ----
            float ps[4] = {0.f, 0.f, 0.f, 0.f};
#pragma unroll
            for (int ks = 0; ks < 4; ks++) {
                const int pb = ks * 8;
                uint32_t a0 = pack_f16(s[2 * ks][0], s[2 * ks][1]);
                uint32_t a1 = pack_f16(s[2 * ks][2], s[2 * ks][3]);
                uint32_t a2 = pack_f16(s[2 * ks + 1][0], s[2 * ks + 1][1]);
                uint32_t a3 = pack_f16(s[2 * ks + 1][2], s[2 * ks + 1][3]);
                mma16(ps, a0, a1, a2, a3, ONES, ONES);
#pragma unroll
                for (int nt = 0; nt < 8; nt++) {
                    uint2 b0 = V2s[(nt * 8 + gid) * ST + pb + tig];
                    uint2 b1 = V2s[(nt * 8 + gid) * ST + pb + tig + 4];
                    mma2(o[nt], a0, a1, a2, a3, b0, b1);
                }
            }
            l0 += ps[0];
            l1 += ps[2];

            __syncthreads();     // all warps done with buf (kt&1)
            if (kt + 2 <= qt) issue_kv(kt + 2, kt & 1);
            CP_COMMIT();         // uniform group count
        }

        const float inv0 = 1.f / l0;
        const float inv1 = 1.f / l1;
#pragma unroll
        for (int nt = 0; nt < 8; nt++) {
            int c = nt * 8 + 2 * tig;
            *(float2*)&out[(size_t)((size_t)b * S_ + row0) * H_ + c] =
                make_float2(o[nt][0] * inv0, o[nt][1] * inv0);
            *(float2*)&out[(size_t)((size_t)b * S_ + row1) * H_ + c] =
                make_float2(o[nt][2] * inv1, o[nt][3] * inv1);
        }
    }
}

// ---------------------------------------------------------------------------
extern "C" void kernel_launch(void* const* d_in, const int* in_sizes, int n_in,
                              void* d_out, int out_size)
{
    const float* x  = (const float*)d_in[0];
    const float* Wq = (const float*)d_in[1];
    const float* Wk = (const float*)d_in[2];
    const float* Wv = (const float*)d_in[3];
    float* out = (float*)d_out;
    (void)in_sizes; (void)n_in; (void)out_size;

    wsplit_kernel<<<384, 256>>>(Wq, Wk, Wv);

    const int qkv_smem = 3 * (128 * 40 * 4 + 64 * 20 * 8);  // 92160
    cudaFuncSetAttribute(qkv_kernel,
                         cudaFuncAttributeMaxDynamicSharedMemorySize, qkv_smem);
    qkv_kernel<<<dim3(3, 256), 256, qkv_smem>>>(x);

    const int attn_smem = 4 * 64 * 36 * 8;  // 73728: 2K + 2V
    cudaFuncSetAttribute(attn_kernel,
                         cudaFuncAttributeMaxDynamicSharedMemorySize, attn_smem);
    attn_kernel<<<256, 128, attn_smem>>>(out);
}